// round 16
// baseline (speedup 1.0000x reference)
#include <cuda_runtime.h>
#include <math.h>

#define B       16
#define N       128
#define NC      80
#define HW0     25600
#define HW1     6400
#define HW2     1600
#define CHUNK   800                  // MUST stay <= 1024 (10-bit local idx)
#define NITER   (CHUNK / 32)         // 25 pred iters per block
#define NTUP    (3 * B * N)          // 6144 tuples
#define CH0     (HW0 / CHUNK)        // 32
#define CH1     (HW1 / CHUNK)        // 8
#define CH2     (HW2 / CHUNK)        // 2
#define NCHUNKS (CH0 + CH1 + CH2)    // 42
#define GBLOCKS (NTUP / 16)          // 384 gather blocks total (8 warps x 2 tuples)
#define GB0     (2 * B * N / 16)     // 128 gather blocks for level 0
#define GB12    (GBLOCKS - GB0)      // 256 gather blocks for levels 1+2

// Scratch (no device allocations allowed).
__device__ unsigned long long g_part[B][N][NCHUNKS];  // transposed: keys contiguous per (b,g)
__device__ float        g_blk[3][GBLOCKS];            // per-block loss partials
__device__ unsigned int g_count;                      // cross-kernel ticket (zero-init; reset each run)

// ---------------------------------------------------------------------------
// Kernel 1: per-chunk nearest-pred search (R13 VERBATIM math -- best known).
// bxoff selects the level subset: launch A covers slots [0,CH0), launch B
// covers [CH0, NCHUNKS).  float2 loads + 5-deep prefetch; direct d2;
//   key = (d2_bits & 0xFFFFFC00) | p_local ; kmin = umin(kmin, key)
// ---------------------------------------------------------------------------
__global__ __launch_bounds__(256)
void argmin_kernel(const float* __restrict__ reg0,
                   const float* __restrict__ reg1,
                   const float* __restrict__ reg2,
                   const float* __restrict__ gt,
                   int bxoff) {
    const int bx = blockIdx.x + bxoff;   // chunk slot 0..41
    const int b  = blockIdx.y;
    const int gh = blockIdx.z;           // gt half

    int chunk, HW;
    const float* reg;
    if (bx < CH0)            { chunk = bx;               HW = HW0; reg = reg0; }
    else if (bx < CH0 + CH1) { chunk = bx - CH0;         HW = HW1; reg = reg1; }
    else                     { chunk = bx - (CH0 + CH1); HW = HW2; reg = reg2; }

    const int tx = threadIdx.x & 31;
    const int ty = threadIdx.x >> 5;           // 0..7
    const int gbase = gh * 64 + ty * 8;        // first of this thread's 8 gts

    float gx[8], gy[8];
    unsigned kmin[8];
    const float* gtb = gt + ((size_t)b * N + gbase) * 4;
#pragma unroll
    for (int i = 0; i < 8; i++) {
        gx[i] = gtb[i * 4 + 0];
        gy[i] = gtb[i * 4 + 1];
        kmin[i] = 0xFFFFFFFFu;
    }

    // float2 view: pred p's (x,y) is element 2*p (16B row stride, 8B aligned).
    const float2* regb2 = reinterpret_cast<const float2*>(reg + (size_t)b * HW * 4);
    const int pbase = chunk * CHUNK;

    // 5-deep prefetch pipeline over 25 iterations.
    float2 buf[5];
#pragma unroll
    for (int s = 0; s < 5; s++)
        buf[s] = regb2[(size_t)(pbase + s * 32 + tx) * 2];

#pragma unroll 5
    for (int it = 0; it < NITER - 5; it++) {
        float2 v = buf[it % 5];
        buf[it % 5] = regb2[(size_t)(pbase + (it + 5) * 32 + tx) * 2];
        const unsigned plocal = (unsigned)(it * 32) + (unsigned)tx;
#pragma unroll
        for (int i = 0; i < 8; i++) {
            float dx = gx[i] - v.x;
            float dy = gy[i] - v.y;
            float d2 = dx * dx + dy * dy;
            kmin[i] = umin(kmin[i], (__float_as_uint(d2) & 0xFFFFFC00u) | plocal);
        }
    }
#pragma unroll
    for (int it = NITER - 5; it < NITER; it++) {   // drain
        float2 v = buf[it % 5];
        const unsigned plocal = (unsigned)(it * 32) + (unsigned)tx;
#pragma unroll
        for (int i = 0; i < 8; i++) {
            float dx = gx[i] - v.x;
            float dy = gy[i] - v.y;
            float d2 = dx * dx + dy * dy;
            kmin[i] = umin(kmin[i], (__float_as_uint(d2) & 0xFFFFFC00u) | plocal);
        }
    }

    // Warp reduce u32 keys; lane 0 writes u64 partial (trunc_d2, global idx).
#pragma unroll
    for (int i = 0; i < 8; i++) {
        unsigned k = kmin[i];
#pragma unroll
        for (int off = 16; off > 0; off >>= 1)
            k = umin(k, __shfl_xor_sync(0xFFFFFFFFu, k, off));
        if (tx == 0) {
            unsigned idx = (unsigned)pbase + (k & 0x3FFu);
            g_part[b][gbase + i][bx] =
                ((unsigned long long)(k & 0xFFFFFC00u) << 32) | idx;
        }
    }
}

// ---------------------------------------------------------------------------
// Kernel 2: gather + CE/L1 + cross-kernel deterministic reduction (R13 form).
// goff = global gather-block offset (L0 launch: 0 over 128 blocks; L12
// launch: 128 over 256 blocks). TWO tuples per warp. The global ticket spans
// BOTH launches (384 blocks); the overall-last block does the final reduce.
// ---------------------------------------------------------------------------
__global__ __launch_bounds__(256)
void gather_kernel(const float* __restrict__ cls0,
                   const float* __restrict__ cls1,
                   const float* __restrict__ cls2,
                   const float* __restrict__ reg0,
                   const float* __restrict__ reg1,
                   const float* __restrict__ reg2,
                   const float* __restrict__ gt,
                   const int*   __restrict__ labels,
                   float*       __restrict__ out,
                   int goff) {
    const int gid  = blockIdx.x + goff;                 // global gather block 0..383
    const int wib  = threadIdx.x >> 5;
    const int lane = threadIdx.x & 31;
    const int w0   = (gid * 8 + wib) * 2;               // first tuple id
    // w1 = w0 + 1 -- same level always (level boundaries 2048/4096 are even).

    const int lvl = w0 / (B * N);
    const int r0  = w0 - lvl * (B * N);
    const int r1  = r0 + 1;
    const int b0  = r0 / N, g0 = r0 - b0 * N;
    const int b1  = r1 / N, g1 = r1 - b1 * N;

    const float* cls; const float* reg; int HW, s0, nch;
    if (lvl == 0)      { cls = cls0; reg = reg0; HW = HW0; s0 = 0;         nch = CH0; }
    else if (lvl == 1) { cls = cls1; reg = reg1; HW = HW1; s0 = CH0;       nch = CH1; }
    else               { cls = cls2; reg = reg2; HW = HW2; s0 = CH0 + CH1; nch = CH2; }

    unsigned long long keyA = 0xFFFFFFFFFFFFFFFFULL;
    unsigned long long keyB = 0xFFFFFFFFFFFFFFFFULL;
    if (lane < nch) {
        keyA = g_part[b0][g0][s0 + lane];
        keyB = g_part[b1][g1][s0 + lane];
    }
#pragma unroll
    for (int off = 16; off > 0; off >>= 1) {
        unsigned long long a2 = __shfl_xor_sync(0xFFFFFFFFu, keyA, off);
        unsigned long long b2 = __shfl_xor_sync(0xFFFFFFFFu, keyB, off);
        keyA = (a2 < keyA) ? a2 : keyA;
        keyB = (b2 < keyB) ? b2 : keyB;
    }
    const unsigned idA = (unsigned)keyA;
    const unsigned idB = (unsigned)keyB;

    // Issue ALL dependent scalar loads now; consume after the reductions.
    const float* crowA = cls + ((size_t)b0 * HW + idA) * NC;
    const float* crowB = cls + ((size_t)b1 * HW + idB) * NC;
    float4 gA = *reinterpret_cast<const float4*>(gt + ((size_t)b0 * N + g0) * 4);
    float4 gB = *reinterpret_cast<const float4*>(gt + ((size_t)b1 * N + g1) * 4);
    float4 rA = *reinterpret_cast<const float4*>(reg + ((size_t)b0 * HW + idA) * 4);
    float4 rB = *reinterpret_cast<const float4*>(reg + ((size_t)b1 * HW + idB) * 4);
    int labA = labels[b0 * N + g0];
    int labB = labels[b1 * N + g1];
    float logitA = crowA[labA];
    float logitB = crowB[labB];

    const float NEGINF = -__int_as_float(0x7F800000);
    float a0 = NEGINF, a1 = NEGINF, a2v = NEGINF;
    float c0 = NEGINF, c1 = NEGINF, c2v = NEGINF;
    if (lane < NC)      { a0  = crowA[lane];      c0  = crowB[lane]; }
    if (lane + 32 < NC) { a1  = crowA[lane + 32]; c1  = crowB[lane + 32]; }
    if (lane + 64 < NC) { a2v = crowA[lane + 64]; c2v = crowB[lane + 64]; }
    float mxA = fmaxf(a0, fmaxf(a1, a2v));
    float mxB = fmaxf(c0, fmaxf(c1, c2v));
#pragma unroll
    for (int off = 16; off > 0; off >>= 1) {
        mxA = fmaxf(mxA, __shfl_xor_sync(0xFFFFFFFFu, mxA, off));
        mxB = fmaxf(mxB, __shfl_xor_sync(0xFFFFFFFFu, mxB, off));
    }
    float smA = 0.0f, smB = 0.0f;
    if (lane < NC)      { smA += expf(a0  - mxA); smB += expf(c0  - mxB); }
    if (lane + 32 < NC) { smA += expf(a1  - mxA); smB += expf(c1  - mxB); }
    if (lane + 64 < NC) { smA += expf(a2v - mxA); smB += expf(c2v - mxB); }
#pragma unroll
    for (int off = 16; off > 0; off >>= 1) {
        smA += __shfl_xor_sync(0xFFFFFFFFu, smA, off);
        smB += __shfl_xor_sync(0xFFFFFFFFu, smB, off);
    }
    float lseA = mxA + logf(smA);
    float lseB = mxB + logf(smB);

    __shared__ float s_ce[8], s_l1[8], s_w[8];
    __shared__ int   s_last;

    if (lane == 0) {
        float dxA = gA.x - rA.x, dyA = gA.y - rA.y;
        float dxB = gB.x - rB.x, dyB = gB.y - rB.y;
        float d2A = dxA * dxA + dyA * dyA;
        float d2B = dxB * dxB + dyB * dyB;
        float wA = (sqrtf(d2A) < 2.5f) ? 1.0f : 0.0f;
        float wB = (sqrtf(d2B) < 2.5f) ? 1.0f : 0.0f;

        float ceA = lseA - logitA;
        float ceB = lseB - logitB;
        float l1A = fabsf(rA.x - gA.x) + fabsf(rA.y - gA.y) +
                    fabsf(rA.z - gA.z) + fabsf(rA.w - gA.w);
        float l1B = fabsf(rB.x - gB.x) + fabsf(rB.y - gB.y) +
                    fabsf(rB.z - gB.z) + fabsf(rB.w - gB.w);

        s_ce[wib] = ceA * wA + ceB * wB;
        s_l1[wib] = l1A * wA + l1B * wB;
        s_w[wib]  = wA + wB;
    }
    __syncthreads();

    if (threadIdx.x == 0) {
        float a = 0.0f, c = 0.0f, nn = 0.0f;
#pragma unroll
        for (int i = 0; i < 8; i++) { a += s_ce[i]; c += s_l1[i]; nn += s_w[i]; }
        g_blk[0][gid] = a;
        g_blk[1][gid] = c;
        g_blk[2][gid] = nn;
        __threadfence();
        unsigned t = atomicAdd(&g_count, 1u);
        s_last = (t == GBLOCKS - 1);
    }
    __syncthreads();

    if (!s_last) return;
    __threadfence();   // see other kernel's g_blk writes

    // Overall-last gather block (either launch): deterministic final reduce.
    __shared__ float r0s[256], r1s[256], r2s[256];
    int tid = threadIdx.x;
    float a = 0.0f, c = 0.0f, nn = 0.0f;
    for (int i = tid; i < GBLOCKS; i += 256) {
        a  += g_blk[0][i];
        c  += g_blk[1][i];
        nn += g_blk[2][i];
    }
    r0s[tid] = a; r1s[tid] = c; r2s[tid] = nn;
    __syncthreads();
    for (int off = 128; off > 0; off >>= 1) {
        if (tid < off) {
            r0s[tid] += r0s[tid + off];
            r1s[tid] += r1s[tid + off];
            r2s[tid] += r2s[tid + off];
        }
        __syncthreads();
    }
    if (tid == 0) {
        float np    = r2s[0];
        float denom = fmaxf(np, 1.0f);
        out[0] = r0s[0] / denom;
        out[1] = r1s[0] / denom;
        out[2] = np;
        g_count = 0;   // reset ticket for next graph replay
    }
}

// ---------------------------------------------------------------------------
// Two-stream overlap: levels 1+2 (argmin + latency-bound gather) run on a
// non-blocking side stream, hidden under level-0's argmin on the main stream.
// Fork/join via events (standard capturable pattern). Stream/events created
// once on the first (pre-capture correctness) call; reused thereafter --
// deterministic identical work every call.
// Inputs bound BY ELEMENT COUNT (metadata order is interleaved).
// ---------------------------------------------------------------------------
extern "C" void kernel_launch(void* const* d_in, const int* in_sizes, int n_in,
                              void* d_out, int out_size) {
    const float* cls0 = 0; const float* cls1 = 0; const float* cls2 = 0;
    const float* reg0 = 0; const float* reg1 = 0; const float* reg2 = 0;
    const float* gt   = 0; const int*   lab  = 0;

    for (int i = 0; i < n_in; i++) {
        switch (in_sizes[i]) {
            case B * HW0 * NC: cls0 = (const float*)d_in[i]; break;  // 32,768,000
            case B * HW1 * NC: cls1 = (const float*)d_in[i]; break;  //  8,192,000
            case B * HW2 * NC: cls2 = (const float*)d_in[i]; break;  //  2,048,000
            case B * HW0 * 4:  reg0 = (const float*)d_in[i]; break;  //  1,638,400
            case B * HW1 * 4:  reg1 = (const float*)d_in[i]; break;  //    409,600
            case B * HW2 * 4:  reg2 = (const float*)d_in[i]; break;  //    102,400
            case B * N * 4:    gt   = (const float*)d_in[i]; break;  //      8,192
            case B * N:        lab  = (const int*)d_in[i];   break;  //      2,048
        }
    }
    float* out = (float*)d_out;

    static cudaStream_t s1 = 0;
    static cudaEvent_t  evF = 0, evJ = 0;
    if (!s1) {
        cudaStreamCreateWithFlags(&s1, cudaStreamNonBlocking);
        cudaEventCreateWithFlags(&evF, cudaEventDisableTiming);
        cudaEventCreateWithFlags(&evJ, cudaEventDisableTiming);
    }

    // Fork: side stream handles levels 1+2 end-to-end.
    cudaEventRecord(evF, 0);
    cudaStreamWaitEvent(s1, evF, 0);

    dim3 g12(CH1 + CH2, B, 2);          // 320 blocks
    argmin_kernel<<<g12, 256, 0, s1>>>(reg0, reg1, reg2, gt, CH0);
    gather_kernel<<<GB12, 256, 0, s1>>>(cls0, cls1, cls2, reg0, reg1, reg2,
                                        gt, lab, out, GB0);
    cudaEventRecord(evJ, s1);

    // Main stream: level 0 (the long pole).
    dim3 g0(CH0, B, 2);                 // 1024 blocks
    argmin_kernel<<<g0, 256>>>(reg0, reg1, reg2, gt, 0);
    gather_kernel<<<GB0, 256>>>(cls0, cls1, cls2, reg0, reg1, reg2,
                                gt, lab, out, 0);

    // Join side stream back into the captured stream.
    cudaStreamWaitEvent(0, evJ, 0);
}